// round 5
// baseline (speedup 1.0000x reference)
#include <cuda_runtime.h>
#include <cstdint>

#define BB   32
#define NN   512
#define DD   256
#define HH   8
#define HDIM 32
#define EE   16384
#define ETOT (EE + NN)

// ---------------- scratch (static device globals; no allocation) -------------
__device__ float g_xwq[BB * NN * DD];
__device__ float g_xwk[BB * NN * DD];
__device__ float g_xwv[BB * NN * DD];
__device__ float g_Q  [BB * NN * DD];
__device__ float g_K  [BB * NN * DD];
__device__ float g_V  [BB * NN * DD];
__device__ float g_att[BB * NN * DD];
__device__ int   g_rowptr[NN + 1];
__device__ int2  g_edge[ETOT];       // (src, norm-as-int)

// ---------------- helpers -----------------------------------------------------
__device__ __forceinline__ uint32_t f2tf32(float f) {
    uint32_t r;
    asm("cvt.rna.tf32.f32 %0, %1;" : "=r"(r) : "f"(f));
    return r;
}

// ---------------- fused single-CTA graph prep ---------------------------------
// detect dtype, degree count, prefix scan, CSR fill — all in one block.
__global__ __launch_bounds__(NN) void k_graph(const int* __restrict__ edge) {
    __shared__ int sdeg[NN];
    __shared__ int scnt[NN];
    __shared__ int srow[NN];
    __shared__ int ss[NN];
    __shared__ int se64;
    int t = threadIdx.x;

    if (t == 0) {
        int nz = 0;
        for (int i = 0; i < 64; i++) nz += (edge[2 * i + 1] != 0);
        se64 = (nz == 0) ? 1 : 0;
    }
    sdeg[t] = 0;
    scnt[t] = 0;
    __syncthreads();
    int e64 = se64;

    for (int e = t; e < ETOT; e += NN) {
        int dst = (e < EE) ? (e64 ? edge[2 * (EE + e)] : edge[EE + e]) : (e - EE);
        if (dst >= 0 && dst < NN) atomicAdd(&sdeg[dst], 1);
    }
    __syncthreads();

    ss[t] = sdeg[t];
    __syncthreads();
    for (int off = 1; off < NN; off <<= 1) {
        int v = (t >= off) ? ss[t - off] : 0;
        __syncthreads();
        ss[t] += v;
        __syncthreads();
    }
    srow[t] = ss[t] - sdeg[t];           // exclusive
    g_rowptr[t + 1] = ss[t];
    if (t == 0) g_rowptr[0] = 0;
    __syncthreads();

    for (int e = t; e < ETOT; e += NN) {
        int s, d;
        if (e < EE) {
            s = e64 ? edge[2 * e] : edge[e];
            d = e64 ? edge[2 * (EE + e)] : edge[EE + e];
        } else {
            s = e - EE; d = e - EE;
        }
        if (s < 0 || s >= NN || d < 0 || d >= NN) continue;
        float nm = rsqrtf((float)sdeg[s]) * rsqrtf((float)sdeg[d]);
        int pos = srow[d] + atomicAdd(&scnt[d], 1);
        g_edge[pos] = make_int2(s, __float_as_int(nm));
    }
}

// ---------------- tf32 mma.sync GEMM ------------------------------------------
#define AS_STRIDE 36
#define BS_STRIDE 132

__global__ __launch_bounds__(256) void k_gemm_mma(
    const float* __restrict__ a0p, const float* __restrict__ a1p,
    const float* __restrict__ a2p,
    const float* __restrict__ w0, const float* __restrict__ w1,
    const float* __restrict__ w2,
    float* __restrict__ c0p, float* __restrict__ c1p, float* __restrict__ c2p,
    const float* __restrict__ bias)
{
    __shared__ uint32_t As[128 * AS_STRIDE];
    __shared__ uint32_t Bs[32 * BS_STRIDE];
    __shared__ float    bsh[128];

    const int z = blockIdx.z;
    const float* A  = (z == 0) ? a0p : (z == 1) ? a1p : a2p;
    const float* Wm = (z == 0) ? w0  : (z == 1) ? w1  : w2;
    float*       C  = (z == 0) ? c0p : (z == 1) ? c1p : c2p;

    const int n0 = blockIdx.x * 128;
    const int m0 = blockIdx.y * 128;

    int tid  = threadIdx.x;
    int wid  = tid >> 5;
    int lane = tid & 31;
    int grp  = lane >> 2;
    int tig  = lane & 3;
    int wm   = (wid & 1) * 64;
    int wn   = (wid >> 1) * 32;

    if (tid < 128) bsh[tid] = bias ? bias[n0 + tid] : 0.f;

    float acc[4][4][4];
    #pragma unroll
    for (int i = 0; i < 4; i++)
        #pragma unroll
        for (int j = 0; j < 4; j++)
            #pragma unroll
            for (int r = 0; r < 4; r++) acc[i][j][r] = 0.f;

    for (int k0 = 0; k0 < 256; k0 += 32) {
        #pragma unroll
        for (int t = 0; t < 4; t++) {
            int i   = tid + t * 256;
            int row = i >> 3;
            int q   = (i & 7) * 4;
            float4 v = *(const float4*)(A + (size_t)(m0 + row) * 256 + k0 + q);
            uint4 u;
            u.x = f2tf32(v.x); u.y = f2tf32(v.y);
            u.z = f2tf32(v.z); u.w = f2tf32(v.w);
            *(uint4*)(As + row * AS_STRIDE + q) = u;
        }
        #pragma unroll
        for (int t = 0; t < 4; t++) {
            int i = tid + t * 256;
            int k = i >> 5;
            int q = (i & 31) * 4;
            float4 v = *(const float4*)(Wm + (size_t)(k0 + k) * 256 + n0 + q);
            uint4 u;
            u.x = f2tf32(v.x); u.y = f2tf32(v.y);
            u.z = f2tf32(v.z); u.w = f2tf32(v.w);
            *(uint4*)(Bs + k * BS_STRIDE + q) = u;
        }
        __syncthreads();

        #pragma unroll
        for (int ks = 0; ks < 4; ks++) {
            int kk = ks * 8;
            uint32_t af[4][4], bf[4][2];
            #pragma unroll
            for (int mt = 0; mt < 4; mt++) {
                int r = wm + mt * 16 + grp;
                af[mt][0] = As[r * AS_STRIDE + kk + tig];
                af[mt][1] = As[(r + 8) * AS_STRIDE + kk + tig];
                af[mt][2] = As[r * AS_STRIDE + kk + tig + 4];
                af[mt][3] = As[(r + 8) * AS_STRIDE + kk + tig + 4];
            }
            #pragma unroll
            for (int nt = 0; nt < 4; nt++) {
                int c = wn + nt * 8 + grp;
                bf[nt][0] = Bs[(kk + tig) * BS_STRIDE + c];
                bf[nt][1] = Bs[(kk + tig + 4) * BS_STRIDE + c];
            }
            #pragma unroll
            for (int mt = 0; mt < 4; mt++)
                #pragma unroll
                for (int nt = 0; nt < 4; nt++)
                    asm volatile(
                        "mma.sync.aligned.m16n8k8.row.col.f32.tf32.tf32.f32 "
                        "{%0,%1,%2,%3}, {%4,%5,%6,%7}, {%8,%9}, {%0,%1,%2,%3};"
                        : "+f"(acc[mt][nt][0]), "+f"(acc[mt][nt][1]),
                          "+f"(acc[mt][nt][2]), "+f"(acc[mt][nt][3])
                        : "r"(af[mt][0]), "r"(af[mt][1]),
                          "r"(af[mt][2]), "r"(af[mt][3]),
                          "r"(bf[nt][0]), "r"(bf[nt][1]));
        }
        __syncthreads();
    }

    #pragma unroll
    for (int mt = 0; mt < 4; mt++) {
        #pragma unroll
        for (int nt = 0; nt < 4; nt++) {
            int cc = wn + nt * 8 + tig * 2;
            float b0 = bsh[cc], b1 = bsh[cc + 1];
            size_t r0 = (size_t)(m0 + wm + mt * 16 + grp) * 256 + n0 + cc;
            size_t r1 = r0 + 8 * 256;
            float2 v0 = {acc[mt][nt][0] + b0, acc[mt][nt][1] + b1};
            float2 v1 = {acc[mt][nt][2] + b0, acc[mt][nt][3] + b1};
            *(float2*)(C + r0) = v0;
            *(float2*)(C + r1) = v1;
        }
    }
}

// ---------------- GCN aggregation: smem-cached gather, ILP4 -------------------
#define XS_STRIDE 68
#define AGG_SMEM (NN * XS_STRIDE * 4)

__global__ __launch_bounds__(256) void k_agg3(
    const float* __restrict__ xq, const float* __restrict__ xk,
    const float* __restrict__ xv,
    const float* __restrict__ bq, const float* __restrict__ bk,
    const float* __restrict__ bv,
    float* __restrict__ oq, float* __restrict__ ok_, float* __restrict__ ov)
{
    extern __shared__ float xs[];
    int dq = blockIdx.x;
    int b  = blockIdx.y;
    int z  = blockIdx.z;
    const float* xw   = (z == 0) ? xq : (z == 1) ? xk : xv;
    const float* bias = (z == 0) ? bq : (z == 1) ? bk : bv;
    float*       out  = (z == 0) ? oq : (z == 1) ? ok_ : ov;

    int tid = threadIdx.x;
    const float* base = xw + (size_t)b * NN * DD + dq * 64;

    #pragma unroll
    for (int t = 0; t < 32; t++) {
        int i = tid + t * 256;
        int n = i >> 4;
        int f = (i & 15) * 4;
        *(float4*)(xs + n * XS_STRIDE + f) =
            *(const float4*)(base + (size_t)n * 256 + f);
    }
    __syncthreads();

    int d  = tid & 63;
    int ns = tid >> 6;
    float bb = bias[dq * 64 + d];
    const int2* ge = g_edge;
    for (int n = ns * 128; n < ns * 128 + 128; n++) {
        int s0 = g_rowptr[n], s1 = g_rowptr[n + 1];
        float a0 = 0.f, a1 = 0.f, a2 = 0.f, a3 = 0.f;
        int i = s0;
        for (; i + 4 <= s1; i += 4) {
            int2 e0 = ge[i], e1 = ge[i + 1], e2 = ge[i + 2], e3 = ge[i + 3];
            a0 += __int_as_float(e0.y) * xs[e0.x * XS_STRIDE + d];
            a1 += __int_as_float(e1.y) * xs[e1.x * XS_STRIDE + d];
            a2 += __int_as_float(e2.y) * xs[e2.x * XS_STRIDE + d];
            a3 += __int_as_float(e3.y) * xs[e3.x * XS_STRIDE + d];
        }
        for (; i < s1; i++) {
            int2 e0 = ge[i];
            a0 += __int_as_float(e0.y) * xs[e0.x * XS_STRIDE + d];
        }
        out[((size_t)b * NN + n) * DD + dq * 64 + d] =
            bb + (a0 + a1) + (a2 + a3);
    }
}

// ---------------- masked attention (full-row softmax, float4 smem paths) ------
#define QT 64
#define KC 64
#define TS 36
#define SMEM_ATTN ((QT * NN + QT * TS + KC * TS + QT) * 4)

__global__ __launch_bounds__(256) void k_attn(const float* __restrict__ Q,
                                              const float* __restrict__ K,
                                              const float* __restrict__ V,
                                              const int* __restrict__ mask,
                                              float* __restrict__ out) {
    extern __shared__ float sm[];
    float* Et   = sm;                    // QT x NN
    float* Qs   = Et + QT * NN;          // QT x TS
    float* Ks   = Qs + QT * TS;          // KC x TS (reused as Vs)
    float* lsum = Ks + KC * TS;          // QT

    int q0 = blockIdx.x * QT;
    int h  = blockIdx.y;
    int b  = blockIdx.z;
    int tid = threadIdx.x;

    const float* Qb = Q + ((size_t)b * NN + q0) * DD + h * HDIM;
    const float* Kb = K + (size_t)b * NN * DD + h * HDIM;
    const float* Vb = V + (size_t)b * NN * DD + h * HDIM;

    const float escale = 0.17677669529663687f;

    // load Q tile (pre-scaled), float4
    #pragma unroll
    for (int t = 0; t < 2; t++) {
        int i = tid + t * 256;       // QT*8 = 512 float4s
        int r = i >> 3, f = (i & 7) * 4;
        float4 v = *(const float4*)(Qb + (size_t)r * DD + f);
        v.x *= escale; v.y *= escale; v.z *= escale; v.w *= escale;
        *(float4*)(Qs + r * TS + f) = v;
    }

    int tr = tid >> 4, tc = tid & 15;

    // phase 1: energies + mask -> Et
    for (int c = 0; c < NN; c += KC) {
        __syncthreads();
        #pragma unroll
        for (int t = 0; t < 2; t++) {
            int i = tid + t * 256;
            int r = i >> 3, f = (i & 7) * 4;
            *(float4*)(Ks + r * TS + f) =
                *(const float4*)(Kb + (size_t)(c + r) * DD + f);
        }
        __syncthreads();
        float acc[4][4];
        #pragma unroll
        for (int i = 0; i < 4; i++)
            #pragma unroll
            for (int j = 0; j < 4; j++) acc[i][j] = 0.f;
        #pragma unroll
        for (int d = 0; d < HDIM; d += 4) {
            float4 q4[4], k4[4];
            #pragma unroll
            for (int i = 0; i < 4; i++)
                q4[i] = *(const float4*)(Qs + (tr * 4 + i) * TS + d);
            #pragma unroll
            for (int j = 0; j < 4; j++)
                k4[j] = *(const float4*)(Ks + (tc * 4 + j) * TS + d);
            #pragma unroll
            for (int i = 0; i < 4; i++)
                #pragma unroll
                for (int j = 0; j < 4; j++)
                    acc[i][j] += q4[i].x * k4[j].x + q4[i].y * k4[j].y
                               + q4[i].z * k4[j].z + q4[i].w * k4[j].w;
        }
        #pragma unroll
        for (int i = 0; i < 4; i++) {
            int qg = q0 + tr * 4 + i;
            int kg = c + tc * 4;
            int4 m4 = *(const int4*)(mask + (size_t)qg * NN + kg);
            float4 ev;
            ev.x = m4.x ? acc[i][0] : -1e10f;
            ev.y = m4.y ? acc[i][1] : -1e10f;
            ev.z = m4.z ? acc[i][2] : -1e10f;
            ev.w = m4.w ? acc[i][3] : -1e10f;
            *(float4*)(Et + (tr * 4 + i) * NN + kg) = ev;
        }
    }
    __syncthreads();

    // phase 2: row softmax
    int w = tid >> 5, lane = tid & 31;
    for (int r8 = 0; r8 < 8; r8++) {
        int r = w * 8 + r8;
        float* row = Et + r * NN;
        float m = -3.4e38f;
        #pragma unroll
        for (int t = 0; t < 16; t++) m = fmaxf(m, row[lane + 32 * t]);
        #pragma unroll
        for (int o = 16; o; o >>= 1) m = fmaxf(m, __shfl_xor_sync(0xffffffffu, m, o));
        float s = 0.f;
        #pragma unroll
        for (int t = 0; t < 16; t++) {
            float p = __expf(row[lane + 32 * t] - m);
            row[lane + 32 * t] = p;
            s += p;
        }
        #pragma unroll
        for (int o = 16; o; o >>= 1) s += __shfl_xor_sync(0xffffffffu, s, o);
        if (lane == 0) lsum[r] = s;
    }

    // phase 3: AV (Et rows read as broadcast float4)
    float oacc[8];
    #pragma unroll
    for (int q = 0; q < 8; q++) oacc[q] = 0.f;
    float* Vs = Ks;
    for (int c = 0; c < NN; c += KC) {
        __syncthreads();
        #pragma unroll
        for (int t = 0; t < 2; t++) {
            int i = tid + t * 256;
            int r = i >> 3, f = (i & 7) * 4;
            *(float4*)(Vs + r * TS + f) =
                *(const float4*)(Vb + (size_t)(c + r) * DD + f);
        }
        __syncthreads();
        #pragma unroll 4
        for (int k = 0; k < KC; k += 4) {
            float v0 = Vs[(k + 0) * TS + lane];
            float v1 = Vs[(k + 1) * TS + lane];
            float v2 = Vs[(k + 2) * TS + lane];
            float v3 = Vs[(k + 3) * TS + lane];
            #pragma unroll
            for (int q = 0; q < 8; q++) {
                float4 e4 = *(const float4*)(Et + (size_t)(w * 8 + q) * NN + c + k);
                oacc[q] += e4.x * v0 + e4.y * v1 + e4.z * v2 + e4.w * v3;
            }
        }
    }

    #pragma unroll
    for (int q = 0; q < 8; q++) {
        int r = w * 8 + q;
        out[((size_t)b * NN + q0 + r) * DD + h * HDIM + lane] = oacc[q] / lsum[r];
    }
}

// ---------------- launch ------------------------------------------------------
extern "C" void kernel_launch(void* const* d_in, const int* in_sizes, int n_in,
                              void* d_out, int out_size) {
    const float* query = (const float*)d_in[0];
    const float* key   = (const float*)d_in[1];
    const float* value = (const float*)d_in[2];
    const int*   edge  = (const int*)d_in[3];
    const int*   mask  = (const int*)d_in[4];
    const float* Wq = (const float*)d_in[5];
    const float* bq = (const float*)d_in[6];
    const float* Wk = (const float*)d_in[7];
    const float* bk = (const float*)d_in[8];
    const float* Wv = (const float*)d_in[9];
    const float* bv = (const float*)d_in[10];
    const float* Wo = (const float*)d_in[11];
    const float* bo = (const float*)d_in[12];
    float* out = (float*)d_out;

    float *xwq, *xwk, *xwv, *Qp, *Kp, *Vp, *att;
    cudaGetSymbolAddress((void**)&xwq, g_xwq);
    cudaGetSymbolAddress((void**)&xwk, g_xwk);
    cudaGetSymbolAddress((void**)&xwv, g_xwv);
    cudaGetSymbolAddress((void**)&Qp,  g_Q);
    cudaGetSymbolAddress((void**)&Kp,  g_K);
    cudaGetSymbolAddress((void**)&Vp,  g_V);
    cudaGetSymbolAddress((void**)&att, g_att);

    cudaFuncSetAttribute(k_attn, cudaFuncAttributeMaxDynamicSharedMemorySize,
                         SMEM_ATTN);
    cudaFuncSetAttribute(k_agg3, cudaFuncAttributeMaxDynamicSharedMemorySize,
                         AGG_SMEM);

    // 1: fused graph prep (single CTA)
    k_graph<<<1, NN>>>(edge);

    // 2: fused QKV projection (tf32 tensor cores)
    k_gemm_mma<<<dim3(2, 128, 3), 256>>>(query, key, value,
                                         Wq, Wk, Wv,
                                         xwq, xwk, xwv, nullptr);
    // 3: fused GCN aggregation (+bias)
    k_agg3<<<dim3(4, BB, 3), 256, AGG_SMEM>>>(xwq, xwk, xwv,
                                              bq, bk, bv, Qp, Kp, Vp);

    // 4: masked multi-head attention  (<- ncu capture target)
    k_attn<<<dim3(NN / QT, HH, BB), 256, SMEM_ATTN>>>(Qp, Kp, Vp, mask, att);

    // 5: output projection (+bias) into d_out
    k_gemm_mma<<<dim3(2, 128, 1), 256>>>(att, att, att,
                                         Wo, Wo, Wo,
                                         out, out, out, bo);
}

// round 6
// speedup vs baseline: 1.5010x; 1.5010x over previous
#include <cuda_runtime.h>
#include <cstdint>

#define BB   32
#define NN   512
#define DD   256
#define HH   8
#define HDIM 32
#define EE   16384
#define ETOT (EE + NN)

// ---------------- scratch (static device globals; no allocation) -------------
__device__ float    g_xwq[BB * NN * DD];
__device__ float    g_xwk[BB * NN * DD];
__device__ float    g_xwv[BB * NN * DD];
__device__ float    g_Q  [BB * NN * DD];
__device__ float    g_K  [BB * NN * DD];
__device__ float    g_V  [BB * NN * DD];
__device__ float    g_att[BB * NN * DD];
__device__ int      g_rowptr[NN + 1];
__device__ int2     g_edge[ETOT];          // (src, norm-as-int)
__device__ uint32_t g_bmask[NN * 16];      // packed mask bits

// ---------------- helpers -----------------------------------------------------
__device__ __forceinline__ uint32_t f2tf32(float f) {
    uint32_t r;
    asm("cvt.rna.tf32.f32 %0, %1;" : "=r"(r) : "f"(f));
    return r;
}
__device__ __forceinline__ void mma_tf32(float* c, const uint32_t* a,
                                         uint32_t b0, uint32_t b1) {
    asm volatile(
        "mma.sync.aligned.m16n8k8.row.col.f32.tf32.tf32.f32 "
        "{%0,%1,%2,%3}, {%4,%5,%6,%7}, {%8,%9}, {%0,%1,%2,%3};"
        : "+f"(c[0]), "+f"(c[1]), "+f"(c[2]), "+f"(c[3])
        : "r"(a[0]), "r"(a[1]), "r"(a[2]), "r"(a[3]), "r"(b0), "r"(b1));
}

// ---------------- fused single-CTA graph prep ---------------------------------
__global__ __launch_bounds__(NN) void k_graph(const int* __restrict__ edge) {
    __shared__ int sdeg[NN];
    __shared__ int scnt[NN];
    __shared__ int srow[NN];
    __shared__ int ss[NN];
    __shared__ int se64;
    int t = threadIdx.x;

    if (t == 0) {
        int nz = 0;
        for (int i = 0; i < 64; i++) nz += (edge[2 * i + 1] != 0);
        se64 = (nz == 0) ? 1 : 0;
    }
    sdeg[t] = 0;
    scnt[t] = 0;
    __syncthreads();
    int e64 = se64;

    for (int e = t; e < ETOT; e += NN) {
        int dst = (e < EE) ? (e64 ? edge[2 * (EE + e)] : edge[EE + e]) : (e - EE);
        if (dst >= 0 && dst < NN) atomicAdd(&sdeg[dst], 1);
    }
    __syncthreads();

    ss[t] = sdeg[t];
    __syncthreads();
    for (int off = 1; off < NN; off <<= 1) {
        int v = (t >= off) ? ss[t - off] : 0;
        __syncthreads();
        ss[t] += v;
        __syncthreads();
    }
    srow[t] = ss[t] - sdeg[t];
    g_rowptr[t + 1] = ss[t];
    if (t == 0) g_rowptr[0] = 0;
    __syncthreads();

    for (int e = t; e < ETOT; e += NN) {
        int s, d;
        if (e < EE) {
            s = e64 ? edge[2 * e] : edge[e];
            d = e64 ? edge[2 * (EE + e)] : edge[EE + e];
        } else {
            s = e - EE; d = e - EE;
        }
        if (s < 0 || s >= NN || d < 0 || d >= NN) continue;
        float nm = rsqrtf((float)sdeg[s]) * rsqrtf((float)sdeg[d]);
        int pos = srow[d] + atomicAdd(&scnt[d], 1);
        g_edge[pos] = make_int2(s, __float_as_int(nm));
    }
}

// ---------------- mask bit-packing --------------------------------------------
__global__ void k_pack(const int* __restrict__ mask) {
    int idx = blockIdx.x * 256 + threadIdx.x;   // 8192 words
    int r  = idx >> 4;
    int wd = idx & 15;
    const int* mrow = mask + (size_t)r * NN + wd * 32;
    uint32_t bits = 0;
    #pragma unroll
    for (int j = 0; j < 32; j++) bits |= (mrow[j] ? 1u : 0u) << j;
    g_bmask[idx] = bits;
}

// ---------------- tf32 mma.sync GEMM ------------------------------------------
#define AS_STRIDE 36
#define BS_STRIDE 132

__global__ __launch_bounds__(256) void k_gemm_mma(
    const float* __restrict__ a0p, const float* __restrict__ a1p,
    const float* __restrict__ a2p,
    const float* __restrict__ w0, const float* __restrict__ w1,
    const float* __restrict__ w2,
    float* __restrict__ c0p, float* __restrict__ c1p, float* __restrict__ c2p,
    const float* __restrict__ bias)
{
    __shared__ uint32_t As[128 * AS_STRIDE];
    __shared__ uint32_t Bs[32 * BS_STRIDE];
    __shared__ float    bsh[128];

    const int z = blockIdx.z;
    const float* A  = (z == 0) ? a0p : (z == 1) ? a1p : a2p;
    const float* Wm = (z == 0) ? w0  : (z == 1) ? w1  : w2;
    float*       C  = (z == 0) ? c0p : (z == 1) ? c1p : c2p;

    const int n0 = blockIdx.x * 128;
    const int m0 = blockIdx.y * 128;

    int tid  = threadIdx.x;
    int wid  = tid >> 5;
    int lane = tid & 31;
    int grp  = lane >> 2;
    int tig  = lane & 3;
    int wm   = (wid & 1) * 64;
    int wn   = (wid >> 1) * 32;

    if (tid < 128) bsh[tid] = bias ? bias[n0 + tid] : 0.f;

    float acc[4][4][4];
    #pragma unroll
    for (int i = 0; i < 4; i++)
        #pragma unroll
        for (int j = 0; j < 4; j++)
            #pragma unroll
            for (int r = 0; r < 4; r++) acc[i][j][r] = 0.f;

    for (int k0 = 0; k0 < 256; k0 += 32) {
        #pragma unroll
        for (int t = 0; t < 4; t++) {
            int i   = tid + t * 256;
            int row = i >> 3;
            int q   = (i & 7) * 4;
            float4 v = *(const float4*)(A + (size_t)(m0 + row) * 256 + k0 + q);
            uint4 u;
            u.x = f2tf32(v.x); u.y = f2tf32(v.y);
            u.z = f2tf32(v.z); u.w = f2tf32(v.w);
            *(uint4*)(As + row * AS_STRIDE + q) = u;
        }
        #pragma unroll
        for (int t = 0; t < 4; t++) {
            int i = tid + t * 256;
            int k = i >> 5;
            int q = (i & 31) * 4;
            float4 v = *(const float4*)(Wm + (size_t)(k0 + k) * 256 + n0 + q);
            uint4 u;
            u.x = f2tf32(v.x); u.y = f2tf32(v.y);
            u.z = f2tf32(v.z); u.w = f2tf32(v.w);
            *(uint4*)(Bs + k * BS_STRIDE + q) = u;
        }
        __syncthreads();

        #pragma unroll
        for (int ks = 0; ks < 4; ks++) {
            int kk = ks * 8;
            uint32_t af[4][4], bf[4][2];
            #pragma unroll
            for (int mt = 0; mt < 4; mt++) {
                int r = wm + mt * 16 + grp;
                af[mt][0] = As[r * AS_STRIDE + kk + tig];
                af[mt][1] = As[(r + 8) * AS_STRIDE + kk + tig];
                af[mt][2] = As[r * AS_STRIDE + kk + tig + 4];
                af[mt][3] = As[(r + 8) * AS_STRIDE + kk + tig + 4];
            }
            #pragma unroll
            for (int nt = 0; nt < 4; nt++) {
                int c = wn + nt * 8 + grp;
                bf[nt][0] = Bs[(kk + tig) * BS_STRIDE + c];
                bf[nt][1] = Bs[(kk + tig + 4) * BS_STRIDE + c];
            }
            #pragma unroll
            for (int mt = 0; mt < 4; mt++)
                #pragma unroll
                for (int nt = 0; nt < 4; nt++)
                    mma_tf32(acc[mt][nt], af[mt], bf[nt][0], bf[nt][1]);
        }
        __syncthreads();
    }

    #pragma unroll
    for (int mt = 0; mt < 4; mt++) {
        #pragma unroll
        for (int nt = 0; nt < 4; nt++) {
            int cc = wn + nt * 8 + tig * 2;
            float b0 = bsh[cc], b1 = bsh[cc + 1];
            size_t r0 = (size_t)(m0 + wm + mt * 16 + grp) * 256 + n0 + cc;
            size_t r1 = r0 + 8 * 256;
            float2 v0 = {acc[mt][nt][0] + b0, acc[mt][nt][1] + b1};
            float2 v1 = {acc[mt][nt][2] + b0, acc[mt][nt][3] + b1};
            *(float2*)(C + r0) = v0;
            *(float2*)(C + r1) = v1;
        }
    }
}

// ---------------- GCN aggregation: smem-cached gather, ILP4 -------------------
#define XS_STRIDE 68
#define AGG_SMEM (NN * XS_STRIDE * 4)

__global__ __launch_bounds__(256) void k_agg3(
    const float* __restrict__ xq, const float* __restrict__ xk,
    const float* __restrict__ xv,
    const float* __restrict__ bq, const float* __restrict__ bk,
    const float* __restrict__ bv,
    float* __restrict__ oq, float* __restrict__ ok_, float* __restrict__ ov)
{
    extern __shared__ float xs[];
    int dq = blockIdx.x;
    int b  = blockIdx.y;
    int z  = blockIdx.z;
    const float* xw   = (z == 0) ? xq : (z == 1) ? xk : xv;
    const float* bias = (z == 0) ? bq : (z == 1) ? bk : bv;
    float*       out  = (z == 0) ? oq : (z == 1) ? ok_ : ov;

    int tid = threadIdx.x;
    const float* base = xw + (size_t)b * NN * DD + dq * 64;

    #pragma unroll
    for (int t = 0; t < 32; t++) {
        int i = tid + t * 256;
        int n = i >> 4;
        int f = (i & 15) * 4;
        *(float4*)(xs + n * XS_STRIDE + f) =
            *(const float4*)(base + (size_t)n * 256 + f);
    }
    __syncthreads();

    int d  = tid & 63;
    int ns = tid >> 6;
    float bb = bias[dq * 64 + d];
    const int2* ge = g_edge;
    for (int n = ns * 128; n < ns * 128 + 128; n++) {
        int s0 = g_rowptr[n], s1 = g_rowptr[n + 1];
        float a0 = 0.f, a1 = 0.f, a2 = 0.f, a3 = 0.f;
        int i = s0;
        for (; i + 4 <= s1; i += 4) {
            int2 e0 = ge[i], e1 = ge[i + 1], e2 = ge[i + 2], e3 = ge[i + 3];
            a0 += __int_as_float(e0.y) * xs[e0.x * XS_STRIDE + d];
            a1 += __int_as_float(e1.y) * xs[e1.x * XS_STRIDE + d];
            a2 += __int_as_float(e2.y) * xs[e2.x * XS_STRIDE + d];
            a3 += __int_as_float(e3.y) * xs[e3.x * XS_STRIDE + d];
        }
        for (; i < s1; i++) {
            int2 e0 = ge[i];
            a0 += __int_as_float(e0.y) * xs[e0.x * XS_STRIDE + d];
        }
        out[((size_t)b * NN + n) * DD + dq * 64 + d] =
            bb + (a0 + a1) + (a2 + a3);
    }
}

// ---------------- flash attention on tf32 mma.sync ----------------------------
// CTA: 128 q-rows x one (b,h). 8 warps x m16. KV chunks of 64.
#define KV_ST 36
#define P_ST  68
#define ATT_SMEM ((64 * KV_ST * 2 + 8 * 16 * P_ST) * 4)

__global__ __launch_bounds__(256, 2) void k_attn(
    const float* __restrict__ Q, const float* __restrict__ K,
    const float* __restrict__ V, float* __restrict__ out)
{
    extern __shared__ float sm[];
    uint32_t* Ks = (uint32_t*)sm;                 // 64 x KV_ST (tf32)
    uint32_t* Vs = Ks + 64 * KV_ST;               // 64 x KV_ST (tf32)
    uint32_t* Ps = Vs + 64 * KV_ST;               // 8 warps x 16 x P_ST (tf32)

    int h   = blockIdx.y;
    int b   = blockIdx.z;
    int tid = threadIdx.x;
    int wid = tid >> 5, lane = tid & 31;
    int grp = lane >> 2, tig = lane & 3;
    int qw  = blockIdx.x * 128 + wid * 16;
    uint32_t* Pw = Ps + wid * 16 * P_ST;

    const float* Qb = Q + (size_t)b * NN * DD + h * HDIM;
    const float* Kb = K + (size_t)b * NN * DD + h * HDIM;
    const float* Vb = V + (size_t)b * NN * DD + h * HDIM;

    const float escale = 0.17677669529663687f;   // 1/sqrt(HD)

    // Q a-fragments in registers (4 k-frags x 4 regs), pre-scaled tf32
    uint32_t qa[4][4];
    #pragma unroll
    for (int kf = 0; kf < 4; kf++) {
        int cl = kf * 8 + tig;
        qa[kf][0] = f2tf32(Qb[(size_t)(qw + grp) * DD + cl] * escale);
        qa[kf][1] = f2tf32(Qb[(size_t)(qw + grp + 8) * DD + cl] * escale);
        qa[kf][2] = f2tf32(Qb[(size_t)(qw + grp) * DD + cl + 4] * escale);
        qa[kf][3] = f2tf32(Qb[(size_t)(qw + grp + 8) * DD + cl + 4] * escale);
    }

    float m0 = -3.4e38f, m1 = -3.4e38f, l0 = 0.f, l1 = 0.f;
    float oacc[4][4];
    #pragma unroll
    for (int nt = 0; nt < 4; nt++)
        #pragma unroll
        for (int r = 0; r < 4; r++) oacc[nt][r] = 0.f;

    const uint32_t* bm0 = g_bmask + (size_t)(qw + grp) * 16;
    const uint32_t* bm1 = g_bmask + (size_t)(qw + grp + 8) * 16;

    for (int c0 = 0; c0 < NN; c0 += 64) {
        __syncthreads();
        // stage K,V chunk as tf32, [kv][d] stride KV_ST
        #pragma unroll
        for (int t = 0; t < 2; t++) {
            int i = tid + t * 256;
            int r = i >> 3, f = (i & 7) * 4;
            float4 kv = *(const float4*)(Kb + (size_t)(c0 + r) * DD + f);
            float4 vv = *(const float4*)(Vb + (size_t)(c0 + r) * DD + f);
            uint4 ku, vu;
            ku.x = f2tf32(kv.x); ku.y = f2tf32(kv.y);
            ku.z = f2tf32(kv.z); ku.w = f2tf32(kv.w);
            vu.x = f2tf32(vv.x); vu.y = f2tf32(vv.y);
            vu.z = f2tf32(vv.z); vu.w = f2tf32(vv.w);
            *(uint4*)(Ks + r * KV_ST + f) = ku;
            *(uint4*)(Vs + r * KV_ST + f) = vu;
        }
        __syncthreads();

        // S = Q K^T  (8 n-frags x 4 k-frags)
        float sacc[8][4];
        #pragma unroll
        for (int nt = 0; nt < 8; nt++)
            #pragma unroll
            for (int r = 0; r < 4; r++) sacc[nt][r] = 0.f;
        #pragma unroll
        for (int nt = 0; nt < 8; nt++)
            #pragma unroll
            for (int kf = 0; kf < 4; kf++) {
                uint32_t b0v = Ks[(nt * 8 + grp) * KV_ST + kf * 8 + tig];
                uint32_t b1v = Ks[(nt * 8 + grp) * KV_ST + kf * 8 + tig + 4];
                mma_tf32(sacc[nt], qa[kf], b0v, b1v);
            }

        // mask via packed bits + chunk max
        uint32_t wa0 = bm0[c0 >> 5], wa1 = bm0[(c0 >> 5) + 1];
        uint32_t wb0 = bm1[c0 >> 5], wb1 = bm1[(c0 >> 5) + 1];
        float cm0 = -3.4e38f, cm1 = -3.4e38f;
        #pragma unroll
        for (int nt = 0; nt < 8; nt++) {
            int j  = nt * 8 + 2 * tig;           // even, 0..62
            uint32_t wa = (j < 32) ? wa0 : wa1;
            uint32_t wb = (j < 32) ? wb0 : wb1;
            int sh = j & 31;
            if (!((wa >> sh) & 1))        sacc[nt][0] = -1e10f;
            if (!((wa >> (sh + 1)) & 1))  sacc[nt][1] = -1e10f;
            if (!((wb >> sh) & 1))        sacc[nt][2] = -1e10f;
            if (!((wb >> (sh + 1)) & 1))  sacc[nt][3] = -1e10f;
            cm0 = fmaxf(cm0, fmaxf(sacc[nt][0], sacc[nt][1]));
            cm1 = fmaxf(cm1, fmaxf(sacc[nt][2], sacc[nt][3]));
        }
        cm0 = fmaxf(cm0, __shfl_xor_sync(0xffffffffu, cm0, 1));
        cm0 = fmaxf(cm0, __shfl_xor_sync(0xffffffffu, cm0, 2));
        cm1 = fmaxf(cm1, __shfl_xor_sync(0xffffffffu, cm1, 1));
        cm1 = fmaxf(cm1, __shfl_xor_sync(0xffffffffu, cm1, 2));

        float nm0 = fmaxf(m0, cm0), nm1 = fmaxf(m1, cm1);
        float f0 = __expf(m0 - nm0), f1 = __expf(m1 - nm1);
        l0 *= f0; l1 *= f1;
        #pragma unroll
        for (int nt = 0; nt < 4; nt++) {
            oacc[nt][0] *= f0; oacc[nt][1] *= f0;
            oacc[nt][2] *= f1; oacc[nt][3] *= f1;
        }
        m0 = nm0; m1 = nm1;

        // probs -> tf32 -> warp-private P tile
        #pragma unroll
        for (int nt = 0; nt < 8; nt++) {
            float p0 = __expf(sacc[nt][0] - nm0);
            float p1 = __expf(sacc[nt][1] - nm0);
            float p2 = __expf(sacc[nt][2] - nm1);
            float p3 = __expf(sacc[nt][3] - nm1);
            l0 += p0 + p1; l1 += p2 + p3;
            uint2 u0, u1;
            u0.x = f2tf32(p0); u0.y = f2tf32(p1);
            u1.x = f2tf32(p2); u1.y = f2tf32(p3);
            *(uint2*)(Pw + grp * P_ST + nt * 8 + 2 * tig) = u0;
            *(uint2*)(Pw + (grp + 8) * P_ST + nt * 8 + 2 * tig) = u1;
        }
        __syncwarp();

        // O += P V  (8 k-steps x 4 n-frags)
        #pragma unroll
        for (int kb = 0; kb < 8; kb++) {
            uint32_t pa[4];
            pa[0] = Pw[grp * P_ST + kb * 8 + tig];
            pa[1] = Pw[(grp + 8) * P_ST + kb * 8 + tig];
            pa[2] = Pw[grp * P_ST + kb * 8 + tig + 4];
            pa[3] = Pw[(grp + 8) * P_ST + kb * 8 + tig + 4];
            #pragma unroll
            for (int nt = 0; nt < 4; nt++) {
                uint32_t b0v = Vs[(kb * 8 + tig) * KV_ST + nt * 8 + grp];
                uint32_t b1v = Vs[(kb * 8 + tig + 4) * KV_ST + nt * 8 + grp];
                mma_tf32(oacc[nt], pa, b0v, b1v);
            }
        }
        __syncwarp();
    }

    l0 += __shfl_xor_sync(0xffffffffu, l0, 1);
    l0 += __shfl_xor_sync(0xffffffffu, l0, 2);
    l1 += __shfl_xor_sync(0xffffffffu, l1, 1);
    l1 += __shfl_xor_sync(0xffffffffu, l1, 2);
    float inv0 = 1.f / l0, inv1 = 1.f / l1;

    float* o0 = out + ((size_t)b * NN + qw + grp) * DD + h * HDIM;
    float* o1 = out + ((size_t)b * NN + qw + grp + 8) * DD + h * HDIM;
    #pragma unroll
    for (int nt = 0; nt < 4; nt++) {
        int cl = nt * 8 + 2 * tig;
        float2 v0 = {oacc[nt][0] * inv0, oacc[nt][1] * inv0};
        float2 v1 = {oacc[nt][2] * inv1, oacc[nt][3] * inv1};
        *(float2*)(o0 + cl) = v0;
        *(float2*)(o1 + cl) = v1;
    }
}

// ---------------- launch ------------------------------------------------------
extern "C" void kernel_launch(void* const* d_in, const int* in_sizes, int n_in,
                              void* d_out, int out_size) {
    const float* query = (const float*)d_in[0];
    const float* key   = (const float*)d_in[1];
    const float* value = (const float*)d_in[2];
    const int*   edge  = (const int*)d_in[3];
    const int*   mask  = (const int*)d_in[4];
    const float* Wq = (const float*)d_in[5];
    const float* bq = (const float*)d_in[6];
    const float* Wk = (const float*)d_in[7];
    const float* bk = (const float*)d_in[8];
    const float* Wv = (const float*)d_in[9];
    const float* bv = (const float*)d_in[10];
    const float* Wo = (const float*)d_in[11];
    const float* bo = (const float*)d_in[12];
    float* out = (float*)d_out;

    float *xwq, *xwk, *xwv, *Qp, *Kp, *Vp, *att;
    cudaGetSymbolAddress((void**)&xwq, g_xwq);
    cudaGetSymbolAddress((void**)&xwk, g_xwk);
    cudaGetSymbolAddress((void**)&xwv, g_xwv);
    cudaGetSymbolAddress((void**)&Qp,  g_Q);
    cudaGetSymbolAddress((void**)&Kp,  g_K);
    cudaGetSymbolAddress((void**)&Vp,  g_V);
    cudaGetSymbolAddress((void**)&att, g_att);

    cudaFuncSetAttribute(k_attn, cudaFuncAttributeMaxDynamicSharedMemorySize,
                         ATT_SMEM);
    cudaFuncSetAttribute(k_agg3, cudaFuncAttributeMaxDynamicSharedMemorySize,
                         AGG_SMEM);

    // 1-2: graph prep + mask packing
    k_graph<<<1, NN>>>(edge);
    k_pack<<<32, 256>>>(mask);

    // 3: fused QKV projection (tf32 tensor cores)
    k_gemm_mma<<<dim3(2, 128, 3), 256>>>(query, key, value,
                                         Wq, Wk, Wv,
                                         xwq, xwk, xwv, nullptr);
    // 4: fused GCN aggregation (+bias)
    k_agg3<<<dim3(4, BB, 3), 256, AGG_SMEM>>>(xwq, xwk, xwv,
                                              bq, bk, bv, Qp, Kp, Vp);

    // 5: flash attention (tf32 mma)
    k_attn<<<dim3(4, HH, BB), 256, ATT_SMEM>>>(Qp, Kp, Vp, att);

    // 6: output projection (+bias) into d_out
    k_gemm_mma<<<dim3(2, 128, 1), 256>>>(att, att, att,
                                         Wo, Wo, Wo,
                                         out, out, out, bo);
}

// round 7
// speedup vs baseline: 3.5305x; 2.3521x over previous
#include <cuda_runtime.h>
#include <cstdint>

#define BB   32
#define NN   512
#define DD   256
#define HH   8
#define HDIM 32
#define EE   16384
#define ETOT (EE + NN)

// ---------------- scratch (static device globals; no allocation) -------------
__device__ float    g_xwq[BB * NN * DD];
__device__ float    g_xwk[BB * NN * DD];
__device__ float    g_xwv[BB * NN * DD];
__device__ float    g_Q  [BB * NN * DD];
__device__ float    g_K  [BB * NN * DD];
__device__ float    g_V  [BB * NN * DD];
__device__ float    g_att[BB * NN * DD];
__device__ int      g_rowptr[NN + 1];
__device__ int2     g_edge[ETOT];          // (src, norm-as-int)
__device__ uint32_t g_bmask[NN * 16];      // packed mask bits
__device__ float    g_A[NN * NN];          // dense normalized adjacency

// ---------------- helpers -----------------------------------------------------
__device__ __forceinline__ uint32_t f2tf32(float f) {
    uint32_t r;
    asm("cvt.rna.tf32.f32 %0, %1;" : "=r"(r) : "f"(f));
    return r;
}
__device__ __forceinline__ void mma_tf32(float* c, const uint32_t* a,
                                         uint32_t b0, uint32_t b1) {
    asm volatile(
        "mma.sync.aligned.m16n8k8.row.col.f32.tf32.tf32.f32 "
        "{%0,%1,%2,%3}, {%4,%5,%6,%7}, {%8,%9}, {%0,%1,%2,%3};"
        : "+f"(c[0]), "+f"(c[1]), "+f"(c[2]), "+f"(c[3])
        : "r"(a[0]), "r"(a[1]), "r"(a[2]), "r"(a[3]), "r"(b0), "r"(b1));
}

// ---------------- fused single-CTA graph prep + dense A build -----------------
__global__ __launch_bounds__(NN) void k_graph(const int* __restrict__ edge) {
    __shared__ int sdeg[NN];
    __shared__ int scnt[NN];
    __shared__ int srow[NN];
    __shared__ int ss[NN];
    __shared__ int se64;
    int t = threadIdx.x;

    if (t == 0) {
        int nz = 0;
        for (int i = 0; i < 64; i++) nz += (edge[2 * i + 1] != 0);
        se64 = (nz == 0) ? 1 : 0;
    }
    sdeg[t] = 0;
    scnt[t] = 0;
    __syncthreads();
    int e64 = se64;

    for (int e = t; e < ETOT; e += NN) {
        int dst = (e < EE) ? (e64 ? edge[2 * (EE + e)] : edge[EE + e]) : (e - EE);
        if (dst >= 0 && dst < NN) atomicAdd(&sdeg[dst], 1);
    }
    __syncthreads();

    ss[t] = sdeg[t];
    __syncthreads();
    for (int off = 1; off < NN; off <<= 1) {
        int v = (t >= off) ? ss[t - off] : 0;
        __syncthreads();
        ss[t] += v;
        __syncthreads();
    }
    srow[t] = ss[t] - sdeg[t];
    g_rowptr[t + 1] = ss[t];
    if (t == 0) g_rowptr[0] = 0;
    __syncthreads();

    for (int e = t; e < ETOT; e += NN) {
        int s, d;
        if (e < EE) {
            s = e64 ? edge[2 * e] : edge[e];
            d = e64 ? edge[2 * (EE + e)] : edge[EE + e];
        } else {
            s = e - EE; d = e - EE;
        }
        if (s < 0 || s >= NN || d < 0 || d >= NN) continue;
        float nm = rsqrtf((float)sdeg[s]) * rsqrtf((float)sdeg[d]);
        int pos = srow[d] + atomicAdd(&scnt[d], 1);
        g_edge[pos] = make_int2(s, __float_as_int(nm));
    }
    __syncthreads();

    // dense A: each thread owns row t (zero + serial fill -> deterministic,
    // duplicate edges accumulate exactly as scatter-add in the reference)
    float4* arow4 = (float4*)(g_A + (size_t)t * NN);
    #pragma unroll 8
    for (int i = 0; i < NN / 4; i++) arow4[i] = make_float4(0.f, 0.f, 0.f, 0.f);
    float* arow = g_A + (size_t)t * NN;
    for (int i = srow[t]; i < ss[t]; i++) {
        int2 e = g_edge[i];
        arow[e.x] += __int_as_float(e.y);
    }
}

// ---------------- mask bit-packing --------------------------------------------
__global__ void k_pack(const int* __restrict__ mask) {
    int idx = blockIdx.x * 256 + threadIdx.x;   // 8192 words
    int r  = idx >> 4;
    int wd = idx & 15;
    const int* mrow = mask + (size_t)r * NN + wd * 32;
    uint32_t bits = 0;
    #pragma unroll
    for (int j = 0; j < 32; j++) bits |= (mrow[j] ? 1u : 0u) << j;
    g_bmask[idx] = bits;
}

// ---------------- tf32 mma.sync GEMM (projections) ----------------------------
#define AS_STRIDE 36
#define BS_STRIDE 132

__global__ __launch_bounds__(256) void k_gemm_mma(
    const float* __restrict__ a0p, const float* __restrict__ a1p,
    const float* __restrict__ a2p,
    const float* __restrict__ w0, const float* __restrict__ w1,
    const float* __restrict__ w2,
    float* __restrict__ c0p, float* __restrict__ c1p, float* __restrict__ c2p,
    const float* __restrict__ bias)
{
    __shared__ uint32_t As[128 * AS_STRIDE];
    __shared__ uint32_t Bs[32 * BS_STRIDE];
    __shared__ float    bsh[128];

    const int z = blockIdx.z;
    const float* A  = (z == 0) ? a0p : (z == 1) ? a1p : a2p;
    const float* Wm = (z == 0) ? w0  : (z == 1) ? w1  : w2;
    float*       C  = (z == 0) ? c0p : (z == 1) ? c1p : c2p;

    const int n0 = blockIdx.x * 128;
    const int m0 = blockIdx.y * 128;

    int tid  = threadIdx.x;
    int wid  = tid >> 5;
    int lane = tid & 31;
    int grp  = lane >> 2;
    int tig  = lane & 3;
    int wm   = (wid & 1) * 64;
    int wn   = (wid >> 1) * 32;

    if (tid < 128) bsh[tid] = bias ? bias[n0 + tid] : 0.f;

    float acc[4][4][4];
    #pragma unroll
    for (int i = 0; i < 4; i++)
        #pragma unroll
        for (int j = 0; j < 4; j++)
            #pragma unroll
            for (int r = 0; r < 4; r++) acc[i][j][r] = 0.f;

    for (int k0 = 0; k0 < 256; k0 += 32) {
        #pragma unroll
        for (int t = 0; t < 4; t++) {
            int i   = tid + t * 256;
            int row = i >> 3;
            int q   = (i & 7) * 4;
            float4 v = *(const float4*)(A + (size_t)(m0 + row) * 256 + k0 + q);
            uint4 u;
            u.x = f2tf32(v.x); u.y = f2tf32(v.y);
            u.z = f2tf32(v.z); u.w = f2tf32(v.w);
            *(uint4*)(As + row * AS_STRIDE + q) = u;
        }
        #pragma unroll
        for (int t = 0; t < 4; t++) {
            int i = tid + t * 256;
            int k = i >> 5;
            int q = (i & 31) * 4;
            float4 v = *(const float4*)(Wm + (size_t)(k0 + k) * 256 + n0 + q);
            uint4 u;
            u.x = f2tf32(v.x); u.y = f2tf32(v.y);
            u.z = f2tf32(v.z); u.w = f2tf32(v.w);
            *(uint4*)(Bs + k * BS_STRIDE + q) = u;
        }
        __syncthreads();

        #pragma unroll
        for (int ks = 0; ks < 4; ks++) {
            int kk = ks * 8;
            uint32_t af[4][4], bf[4][2];
            #pragma unroll
            for (int mt = 0; mt < 4; mt++) {
                int r = wm + mt * 16 + grp;
                af[mt][0] = As[r * AS_STRIDE + kk + tig];
                af[mt][1] = As[(r + 8) * AS_STRIDE + kk + tig];
                af[mt][2] = As[r * AS_STRIDE + kk + tig + 4];
                af[mt][3] = As[(r + 8) * AS_STRIDE + kk + tig + 4];
            }
            #pragma unroll
            for (int nt = 0; nt < 4; nt++) {
                int c = wn + nt * 8 + grp;
                bf[nt][0] = Bs[(kk + tig) * BS_STRIDE + c];
                bf[nt][1] = Bs[(kk + tig + 4) * BS_STRIDE + c];
            }
            #pragma unroll
            for (int mt = 0; mt < 4; mt++)
                #pragma unroll
                for (int nt = 0; nt < 4; nt++)
                    mma_tf32(acc[mt][nt], af[mt], bf[nt][0], bf[nt][1]);
        }
        __syncthreads();
    }

    #pragma unroll
    for (int mt = 0; mt < 4; mt++) {
        #pragma unroll
        for (int nt = 0; nt < 4; nt++) {
            int cc = wn + nt * 8 + tig * 2;
            float b0 = bsh[cc], b1 = bsh[cc + 1];
            size_t r0 = (size_t)(m0 + wm + mt * 16 + grp) * 256 + n0 + cc;
            size_t r1 = r0 + 8 * 256;
            float2 v0 = {acc[mt][nt][0] + b0, acc[mt][nt][1] + b1};
            float2 v1 = {acc[mt][nt][2] + b0, acc[mt][nt][3] + b1};
            *(float2*)(C + r0) = v0;
            *(float2*)(C + r1) = v1;
        }
    }
}

// ---------------- aggregation as dense batched GEMM: out[z][b] = A @ xw[z][b] --
__global__ __launch_bounds__(256) void k_agg_gemm(
    const float* __restrict__ xq, const float* __restrict__ xk,
    const float* __restrict__ xv,
    const float* __restrict__ bq, const float* __restrict__ bk,
    const float* __restrict__ bv,
    float* __restrict__ oq, float* __restrict__ ok_, float* __restrict__ ov)
{
    __shared__ uint32_t As[128 * AS_STRIDE];
    __shared__ uint32_t Bs[32 * BS_STRIDE];
    __shared__ float    bsh[128];

    int zz = blockIdx.z;
    int z  = zz >> 5;
    int b  = zz & 31;
    const float* X    = (z == 0) ? xq : (z == 1) ? xk : xv;
    const float* bias = (z == 0) ? bq : (z == 1) ? bk : bv;
    float*       O    = (z == 0) ? oq : (z == 1) ? ok_ : ov;
    const float* Xb = X + (size_t)b * NN * DD;
    float*       Cb = O + (size_t)b * NN * DD;

    const int n0 = blockIdx.x * 128;
    const int m0 = blockIdx.y * 128;

    int tid  = threadIdx.x;
    int wid  = tid >> 5;
    int lane = tid & 31;
    int grp  = lane >> 2;
    int tig  = lane & 3;
    int wm   = (wid & 1) * 64;
    int wn   = (wid >> 1) * 32;

    if (tid < 128) bsh[tid] = bias[n0 + tid];

    float acc[4][4][4];
    #pragma unroll
    for (int i = 0; i < 4; i++)
        #pragma unroll
        for (int j = 0; j < 4; j++)
            #pragma unroll
            for (int r = 0; r < 4; r++) acc[i][j][r] = 0.f;

    for (int k0 = 0; k0 < NN; k0 += 32) {
        // stage A rows (adjacency, stride NN)
        #pragma unroll
        for (int t = 0; t < 4; t++) {
            int i   = tid + t * 256;
            int row = i >> 3;
            int q   = (i & 7) * 4;
            float4 v = *(const float4*)(g_A + (size_t)(m0 + row) * NN + k0 + q);
            uint4 u;
            u.x = f2tf32(v.x); u.y = f2tf32(v.y);
            u.z = f2tf32(v.z); u.w = f2tf32(v.w);
            *(uint4*)(As + row * AS_STRIDE + q) = u;
        }
        // stage X chunk ([K][N] row-major)
        #pragma unroll
        for (int t = 0; t < 4; t++) {
            int i = tid + t * 256;
            int k = i >> 5;
            int q = (i & 31) * 4;
            float4 v = *(const float4*)(Xb + (size_t)(k0 + k) * 256 + n0 + q);
            uint4 u;
            u.x = f2tf32(v.x); u.y = f2tf32(v.y);
            u.z = f2tf32(v.z); u.w = f2tf32(v.w);
            *(uint4*)(Bs + k * BS_STRIDE + q) = u;
        }
        __syncthreads();

        #pragma unroll
        for (int ks = 0; ks < 4; ks++) {
            int kk = ks * 8;
            uint32_t af[4][4], bf[4][2];
            #pragma unroll
            for (int mt = 0; mt < 4; mt++) {
                int r = wm + mt * 16 + grp;
                af[mt][0] = As[r * AS_STRIDE + kk + tig];
                af[mt][1] = As[(r + 8) * AS_STRIDE + kk + tig];
                af[mt][2] = As[r * AS_STRIDE + kk + tig + 4];
                af[mt][3] = As[(r + 8) * AS_STRIDE + kk + tig + 4];
            }
            #pragma unroll
            for (int nt = 0; nt < 4; nt++) {
                int c = wn + nt * 8 + grp;
                bf[nt][0] = Bs[(kk + tig) * BS_STRIDE + c];
                bf[nt][1] = Bs[(kk + tig + 4) * BS_STRIDE + c];
            }
            #pragma unroll
            for (int mt = 0; mt < 4; mt++)
                #pragma unroll
                for (int nt = 0; nt < 4; nt++)
                    mma_tf32(acc[mt][nt], af[mt], bf[nt][0], bf[nt][1]);
        }
        __syncthreads();
    }

    #pragma unroll
    for (int mt = 0; mt < 4; mt++) {
        #pragma unroll
        for (int nt = 0; nt < 4; nt++) {
            int cc = wn + nt * 8 + tig * 2;
            float b0 = bsh[cc], b1 = bsh[cc + 1];
            size_t r0 = (size_t)(m0 + wm + mt * 16 + grp) * 256 + n0 + cc;
            size_t r1 = r0 + 8 * 256;
            float2 v0 = {acc[mt][nt][0] + b0, acc[mt][nt][1] + b1};
            float2 v1 = {acc[mt][nt][2] + b0, acc[mt][nt][3] + b1};
            *(float2*)(Cb + r0) = v0;
            *(float2*)(Cb + r1) = v1;
        }
    }
}

// ---------------- flash attention on tf32 mma.sync ----------------------------
#define KV_ST 36
#define P_ST  68
#define ATT_SMEM ((64 * KV_ST * 2 + 8 * 16 * P_ST) * 4)

__global__ __launch_bounds__(256, 2) void k_attn(
    const float* __restrict__ Q, const float* __restrict__ K,
    const float* __restrict__ V, float* __restrict__ out)
{
    extern __shared__ float sm[];
    uint32_t* Ks = (uint32_t*)sm;
    uint32_t* Vs = Ks + 64 * KV_ST;
    uint32_t* Ps = Vs + 64 * KV_ST;

    int h   = blockIdx.y;
    int b   = blockIdx.z;
    int tid = threadIdx.x;
    int wid = tid >> 5, lane = tid & 31;
    int grp = lane >> 2, tig = lane & 3;
    int qw  = blockIdx.x * 128 + wid * 16;
    uint32_t* Pw = Ps + wid * 16 * P_ST;

    const float* Qb = Q + (size_t)b * NN * DD + h * HDIM;
    const float* Kb = K + (size_t)b * NN * DD + h * HDIM;
    const float* Vb = V + (size_t)b * NN * DD + h * HDIM;

    const float escale = 0.17677669529663687f;

    uint32_t qa[4][4];
    #pragma unroll
    for (int kf = 0; kf < 4; kf++) {
        int cl = kf * 8 + tig;
        qa[kf][0] = f2tf32(Qb[(size_t)(qw + grp) * DD + cl] * escale);
        qa[kf][1] = f2tf32(Qb[(size_t)(qw + grp + 8) * DD + cl] * escale);
        qa[kf][2] = f2tf32(Qb[(size_t)(qw + grp) * DD + cl + 4] * escale);
        qa[kf][3] = f2tf32(Qb[(size_t)(qw + grp + 8) * DD + cl + 4] * escale);
    }

    float m0 = -3.4e38f, m1 = -3.4e38f, l0 = 0.f, l1 = 0.f;
    float oacc[4][4];
    #pragma unroll
    for (int nt = 0; nt < 4; nt++)
        #pragma unroll
        for (int r = 0; r < 4; r++) oacc[nt][r] = 0.f;

    const uint32_t* bm0 = g_bmask + (size_t)(qw + grp) * 16;
    const uint32_t* bm1 = g_bmask + (size_t)(qw + grp + 8) * 16;

    for (int c0 = 0; c0 < NN; c0 += 64) {
        __syncthreads();
        #pragma unroll
        for (int t = 0; t < 2; t++) {
            int i = tid + t * 256;
            int r = i >> 3, f = (i & 7) * 4;
            float4 kv = *(const float4*)(Kb + (size_t)(c0 + r) * DD + f);
            float4 vv = *(const float4*)(Vb + (size_t)(c0 + r) * DD + f);
            uint4 ku, vu;
            ku.x = f2tf32(kv.x); ku.y = f2tf32(kv.y);
            ku.z = f2tf32(kv.z); ku.w = f2tf32(kv.w);
            vu.x = f2tf32(vv.x); vu.y = f2tf32(vv.y);
            vu.z = f2tf32(vv.z); vu.w = f2tf32(vv.w);
            *(uint4*)(Ks + r * KV_ST + f) = ku;
            *(uint4*)(Vs + r * KV_ST + f) = vu;
        }
        __syncthreads();

        float sacc[8][4];
        #pragma unroll
        for (int nt = 0; nt < 8; nt++)
            #pragma unroll
            for (int r = 0; r < 4; r++) sacc[nt][r] = 0.f;
        #pragma unroll
        for (int nt = 0; nt < 8; nt++)
            #pragma unroll
            for (int kf = 0; kf < 4; kf++) {
                uint32_t b0v = Ks[(nt * 8 + grp) * KV_ST + kf * 8 + tig];
                uint32_t b1v = Ks[(nt * 8 + grp) * KV_ST + kf * 8 + tig + 4];
                mma_tf32(sacc[nt], qa[kf], b0v, b1v);
            }

        uint32_t wa0 = bm0[c0 >> 5], wa1 = bm0[(c0 >> 5) + 1];
        uint32_t wb0 = bm1[c0 >> 5], wb1 = bm1[(c0 >> 5) + 1];
        float cm0 = -3.4e38f, cm1 = -3.4e38f;
        #pragma unroll
        for (int nt = 0; nt < 8; nt++) {
            int j  = nt * 8 + 2 * tig;
            uint32_t wa = (j < 32) ? wa0 : wa1;
            uint32_t wb = (j < 32) ? wb0 : wb1;
            int sh = j & 31;
            if (!((wa >> sh) & 1))        sacc[nt][0] = -1e10f;
            if (!((wa >> (sh + 1)) & 1))  sacc[nt][1] = -1e10f;
            if (!((wb >> sh) & 1))        sacc[nt][2] = -1e10f;
            if (!((wb >> (sh + 1)) & 1))  sacc[nt][3] = -1e10f;
            cm0 = fmaxf(cm0, fmaxf(sacc[nt][0], sacc[nt][1]));
            cm1 = fmaxf(cm1, fmaxf(sacc[nt][2], sacc[nt][3]));
        }
        cm0 = fmaxf(cm0, __shfl_xor_sync(0xffffffffu, cm0, 1));
        cm0 = fmaxf(cm0, __shfl_xor_sync(0xffffffffu, cm0, 2));
        cm1 = fmaxf(cm1, __shfl_xor_sync(0xffffffffu, cm1, 1));
        cm1 = fmaxf(cm1, __shfl_xor_sync(0xffffffffu, cm1, 2));

        float nm0 = fmaxf(m0, cm0), nm1 = fmaxf(m1, cm1);
        float f0 = __expf(m0 - nm0), f1 = __expf(m1 - nm1);
        l0 *= f0; l1 *= f1;
        #pragma unroll
        for (int nt = 0; nt < 4; nt++) {
            oacc[nt][0] *= f0; oacc[nt][1] *= f0;
            oacc[nt][2] *= f1; oacc[nt][3] *= f1;
        }
        m0 = nm0; m1 = nm1;

        #pragma unroll
        for (int nt = 0; nt < 8; nt++) {
            float p0 = __expf(sacc[nt][0] - nm0);
            float p1 = __expf(sacc[nt][1] - nm0);
            float p2 = __expf(sacc[nt][2] - nm1);
            float p3 = __expf(sacc[nt][3] - nm1);
            l0 += p0 + p1; l1 += p2 + p3;
            uint2 u0, u1;
            u0.x = f2tf32(p0); u0.y = f2tf32(p1);
            u1.x = f2tf32(p2); u1.y = f2tf32(p3);
            *(uint2*)(Pw + grp * P_ST + nt * 8 + 2 * tig) = u0;
            *(uint2*)(Pw + (grp + 8) * P_ST + nt * 8 + 2 * tig) = u1;
        }
        __syncwarp();

        #pragma unroll
        for (int kb = 0; kb < 8; kb++) {
            uint32_t pa[4];
            pa[0] = Pw[grp * P_ST + kb * 8 + tig];
            pa[1] = Pw[(grp + 8) * P_ST + kb * 8 + tig];
            pa[2] = Pw[grp * P_ST + kb * 8 + tig + 4];
            pa[3] = Pw[(grp + 8) * P_ST + kb * 8 + tig + 4];
            #pragma unroll
            for (int nt = 0; nt < 4; nt++) {
                uint32_t b0v = Vs[(kb * 8 + tig) * KV_ST + nt * 8 + grp];
                uint32_t b1v = Vs[(kb * 8 + tig + 4) * KV_ST + nt * 8 + grp];
                mma_tf32(oacc[nt], pa, b0v, b1v);
            }
        }
        __syncwarp();
    }

    l0 += __shfl_xor_sync(0xffffffffu, l0, 1);
    l0 += __shfl_xor_sync(0xffffffffu, l0, 2);
    l1 += __shfl_xor_sync(0xffffffffu, l1, 1);
    l1 += __shfl_xor_sync(0xffffffffu, l1, 2);
    float inv0 = 1.f / l0, inv1 = 1.f / l1;

    float* o0 = out + ((size_t)b * NN + qw + grp) * DD + h * HDIM;
    float* o1 = out + ((size_t)b * NN + qw + grp + 8) * DD + h * HDIM;
    #pragma unroll
    for (int nt = 0; nt < 4; nt++) {
        int cl = nt * 8 + 2 * tig;
        float2 v0 = {oacc[nt][0] * inv0, oacc[nt][1] * inv0};
        float2 v1 = {oacc[nt][2] * inv1, oacc[nt][3] * inv1};
        *(float2*)(o0 + cl) = v0;
        *(float2*)(o1 + cl) = v1;
    }
}

// ---------------- launch ------------------------------------------------------
extern "C" void kernel_launch(void* const* d_in, const int* in_sizes, int n_in,
                              void* d_out, int out_size) {
    const float* query = (const float*)d_in[0];
    const float* key   = (const float*)d_in[1];
    const float* value = (const float*)d_in[2];
    const int*   edge  = (const int*)d_in[3];
    const int*   mask  = (const int*)d_in[4];
    const float* Wq = (const float*)d_in[5];
    const float* bq = (const float*)d_in[6];
    const float* Wk = (const float*)d_in[7];
    const float* bk = (const float*)d_in[8];
    const float* Wv = (const float*)d_in[9];
    const float* bv = (const float*)d_in[10];
    const float* Wo = (const float*)d_in[11];
    const float* bo = (const float*)d_in[12];
    float* out = (float*)d_out;

    float *xwq, *xwk, *xwv, *Qp, *Kp, *Vp, *att;
    cudaGetSymbolAddress((void**)&xwq, g_xwq);
    cudaGetSymbolAddress((void**)&xwk, g_xwk);
    cudaGetSymbolAddress((void**)&xwv, g_xwv);
    cudaGetSymbolAddress((void**)&Qp,  g_Q);
    cudaGetSymbolAddress((void**)&Kp,  g_K);
    cudaGetSymbolAddress((void**)&Vp,  g_V);
    cudaGetSymbolAddress((void**)&att, g_att);

    cudaFuncSetAttribute(k_attn, cudaFuncAttributeMaxDynamicSharedMemorySize,
                         ATT_SMEM);

    // 1: graph prep + dense adjacency
    k_graph<<<1, NN>>>(edge);
    // 2: mask packing
    k_pack<<<32, 256>>>(mask);

    // 3: fused QKV projection (tf32 tensor cores)
    k_gemm_mma<<<dim3(2, 128, 3), 256>>>(query, key, value,
                                         Wq, Wk, Wv,
                                         xwq, xwk, xwv, nullptr);

    // 4: aggregation as dense batched GEMM (+bias)  (<- ncu capture slot)
    k_agg_gemm<<<dim3(2, 4, 96), 256>>>(xwq, xwk, xwv,
                                        bq, bk, bv, Qp, Kp, Vp);

    // 5: flash attention (tf32 mma)
    k_attn<<<dim3(4, HH, BB), 256, ATT_SMEM>>>(Qp, Kp, Vp, att);

    // 6: output projection (+bias) into d_out
    k_gemm_mma<<<dim3(2, 128, 1), 256>>>(att, att, att,
                                         Wo, Wo, Wo,
                                         out, out, out, bo);
}